// round 16
// baseline (speedup 1.0000x reference)
#include <cuda_runtime.h>
#include <cuda_fp16.h>
#include <cstdint>
#include <math.h>

// ----------------------------------------------------------------------------
// GCViT block, shapes fixed: B=32, H=8, W=256, C=768, NH=16, HD=48
// windows: wh=8, ww=16 -> N=128 tokens/window, Bw=512, M = 65536 rows
// ----------------------------------------------------------------------------

#define M_ROWS   65536
#define C_DIM    768
#define KV_DIM   1536
#define HID_DIM  3072
#define NHEAD    16
#define HEADD    48
#define NTOK     128
#define NWIN     512

// fp16 activations / weights
__device__ __half g_xln16 [ (size_t)M_ROWS * C_DIM  ];
__device__ __half g_kv16  [ (size_t)M_ROWS * KV_DIM ];
__device__ __half g_ao16  [ (size_t)M_ROWS * C_DIM  ];
__device__ __half g_xa16  [ (size_t)M_ROWS * C_DIM  ];
__device__ __half g_ln216 [ (size_t)M_ROWS * C_DIM  ];
__device__ __half g_hmid16[ (size_t)M_ROWS * HID_DIM];
__device__ __half g_qkvw16[ (size_t)KV_DIM * C_DIM  ];
__device__ __half g_pw16  [ (size_t)C_DIM * C_DIM   ];
__device__ __half g_f1w16 [ (size_t)HID_DIM * C_DIM ];
__device__ __half g_f2w16 [ (size_t)C_DIM * HID_DIM ];
// fp32
__device__ float g_biasN[ NHEAD * NTOK * NTOK ];   // [h][n][m]

// convert sizes (all divisible by 4)
#define CONV_N0 (KV_DIM * C_DIM)
#define CONV_N1 (C_DIM * C_DIM)
#define CONV_N2 (HID_DIM * C_DIM)
#define CONV_N3 (C_DIM * HID_DIM)
#define CONV_TOT4 ((CONV_N0 + CONV_N1 + CONV_N2 + CONV_N3) / 4)
#define CONV_BLOCKS ((CONV_TOT4 + 255) / 256)
#define PRE_GRID (M_ROWS + 128 + CONV_BLOCKS)

// ============================================================================
// merged preamble: LN1+window-partition | bias table | weight converts (x4)
// ============================================================================
__device__ __forceinline__ void conv4(const float* __restrict__ s,
                                      __half* __restrict__ d, int e)
{
    float4 v = *(const float4*)(s + e);
    __half2 h0 = __floats2half2_rn(v.x, v.y);
    __half2 h1 = __floats2half2_rn(v.z, v.w);
    uint2 pk = make_uint2(*(uint32_t*)&h0, *(uint32_t*)&h1);
    *(uint2*)(d + e) = pk;
}

__global__ void preamble_kernel(
    const float* __restrict__ x, const float* __restrict__ g,
    const float* __restrict__ bta, __half* __restrict__ xln16,
    const float* __restrict__ rpb, float* __restrict__ biasN,
    const float* __restrict__ qkvw, __half* __restrict__ qkvw16,
    const float* __restrict__ pw,   __half* __restrict__ pw16,
    const float* __restrict__ f1w,  __half* __restrict__ f1w16,
    const float* __restrict__ f2w,  __half* __restrict__ f2w16)
{
    const int blk = blockIdx.x;
    const int t = threadIdx.x;

    if (blk < M_ROWS) {
        __shared__ float s1[8], s2[8];
        const float* xr = x + (long)blk * C_DIM;
        float v0 = xr[t], v1 = xr[t + 256], v2 = xr[t + 512];
        float a = v0 + v1 + v2;
        float bsq = v0*v0 + v1*v1 + v2*v2;
        #pragma unroll
        for (int o = 16; o > 0; o >>= 1) {
            a   += __shfl_xor_sync(0xffffffffu, a, o);
            bsq += __shfl_xor_sync(0xffffffffu, bsq, o);
        }
        if ((t & 31) == 0) { s1[t >> 5] = a; s2[t >> 5] = bsq; }
        __syncthreads();
        float suma = 0.0f, sumb = 0.0f;
        #pragma unroll
        for (int i = 0; i < 8; i++) { suma += s1[i]; sumb += s2[i]; }
        float mean = suma * (1.0f / 768.0f);
        float var  = sumb * (1.0f / 768.0f) - mean * mean;
        float rstd = rsqrtf(var + 1e-5f);
        int bb = blk >> 11, l = blk & 2047;
        int rh = l >> 8, col = l & 255, wc = col >> 4, rw = col & 15;
        long orow = (long)(bb * 16 + wc) * NTOK + rh * 16 + rw;
        __half* o16 = xln16 + orow * C_DIM;
        o16[t]       = __float2half_rn((v0 - mean) * rstd * g[t]       + bta[t]);
        o16[t + 256] = __float2half_rn((v1 - mean) * rstd * g[t + 256] + bta[t + 256]);
        o16[t + 512] = __float2half_rn((v2 - mean) * rstd * g[t + 512] + bta[t + 512]);
        return;
    }
    if (blk < M_ROWS + 128) {
        if (t < 128) {
            int n = blk - M_ROWS, m = t;
            int drh = (n >> 4) - (m >> 4);
            int drw = (n & 15) - (m & 15);
            int idx = (drh + 7) * 63 + (drw + 31);
            #pragma unroll
            for (int h = 0; h < NHEAD; h++)
                biasN[h * (NTOK*NTOK) + n * NTOK + m] = rpb[idx * NHEAD + h];
        }
        return;
    }
    int i4 = (blk - M_ROWS - 128) * 256 + t;
    int e = i4 * 4;
    if (e < CONV_N0) { conv4(qkvw, qkvw16, e); return; }
    e -= CONV_N0;
    if (e < CONV_N1) { conv4(pw, pw16, e); return; }
    e -= CONV_N1;
    if (e < CONV_N2) { conv4(f1w, f1w16, e); return; }
    e -= CONV_N2;
    if (e < CONV_N3) { conv4(f2w, f2w16, e); }
}

// LayerNorm (LN2): fp16 in/out, 128 threads/row, __half2 vectorized accesses.
__global__ void __launch_bounds__(128) ln2_kernel(
    const __half* __restrict__ x, const float* __restrict__ g,
    const float* __restrict__ bta, __half* __restrict__ out16)
{
    __shared__ float s1[4], s2[4];
    int r = blockIdx.x, t = threadIdx.x;
    const __half2* xr = (const __half2*)(x + (long)r * C_DIM);
    __half2 h0 = xr[t], h1 = xr[t + 128], h2 = xr[t + 256];
    float2 f0 = __half22float2(h0);
    float2 f1 = __half22float2(h1);
    float2 f2 = __half22float2(h2);
    float a = f0.x + f0.y + f1.x + f1.y + f2.x + f2.y;
    float bsq = f0.x*f0.x + f0.y*f0.y + f1.x*f1.x + f1.y*f1.y + f2.x*f2.x + f2.y*f2.y;
    #pragma unroll
    for (int o = 16; o > 0; o >>= 1) {
        a   += __shfl_xor_sync(0xffffffffu, a, o);
        bsq += __shfl_xor_sync(0xffffffffu, bsq, o);
    }
    if ((t & 31) == 0) { s1[t >> 5] = a; s2[t >> 5] = bsq; }
    __syncthreads();
    float suma = s1[0] + s1[1] + s1[2] + s1[3];
    float sumb = s2[0] + s2[1] + s2[2] + s2[3];
    float mean = suma * (1.0f / 768.0f);
    float var  = sumb * (1.0f / 768.0f) - mean * mean;
    float rstd = rsqrtf(var + 1e-5f);

    const float2* gp = (const float2*)g;
    const float2* bp = (const float2*)bta;
    __half2* o16 = (__half2*)(out16 + (long)r * C_DIM);
    float2 g0 = gp[t], g1 = gp[t + 128], g2 = gp[t + 256];
    float2 b0 = bp[t], b1 = bp[t + 128], b2 = bp[t + 256];
    o16[t] = __floats2half2_rn((f0.x - mean) * rstd * g0.x + b0.x,
                               (f0.y - mean) * rstd * g0.y + b0.y);
    o16[t + 128] = __floats2half2_rn((f1.x - mean) * rstd * g1.x + b1.x,
                                     (f1.y - mean) * rstd * g1.y + b1.y);
    o16[t + 256] = __floats2half2_rn((f2.x - mean) * rstd * g2.x + b2.x,
                                     (f2.y - mean) * rstd * g2.y + b2.y);
}

// ============================================================================
// shared PTX helpers
// ============================================================================
__device__ __forceinline__ uint32_t smem_u32(const void* p)
{
    uint32_t a;
    asm("{ .reg .u64 t; cvta.to.shared.u64 t, %1; cvt.u32.u64 %0, t; }"
        : "=r"(a) : "l"(p));
    return a;
}

__device__ __forceinline__ void cp16(uint32_t smem, const void* gmem)
{
    asm volatile("cp.async.cg.shared.global.L2::256B [%0], [%1], 16;"
                 :: "r"(smem), "l"(gmem));
}
#define CP_COMMIT() asm volatile("cp.async.commit_group;")
#define CP_WAIT1()  asm volatile("cp.async.wait_group 1;")
#define CP_WAIT0()  asm volatile("cp.async.wait_group 0;")

__device__ __forceinline__ void ldsm_x4(uint32_t r[4], uint32_t addr)
{
    asm volatile("ldmatrix.sync.aligned.m8n8.x4.shared.b16 {%0,%1,%2,%3}, [%4];"
                 : "=r"(r[0]), "=r"(r[1]), "=r"(r[2]), "=r"(r[3]) : "r"(addr));
}

__device__ __forceinline__ void ldsm_x4_t(uint32_t r[4], uint32_t addr)
{
    asm volatile("ldmatrix.sync.aligned.m8n8.x4.trans.shared.b16 {%0,%1,%2,%3}, [%4];"
                 : "=r"(r[0]), "=r"(r[1]), "=r"(r[2]), "=r"(r[3]) : "r"(addr));
}

__device__ __forceinline__ void mma_fp16(float c[4], const uint32_t a[4],
                                         uint32_t b0, uint32_t b1)
{
    asm volatile(
        "mma.sync.aligned.m16n8k16.row.col.f32.f16.f16.f32 "
        "{%0,%1,%2,%3},{%4,%5,%6,%7},{%8,%9},{%0,%1,%2,%3};"
        : "+f"(c[0]), "+f"(c[1]), "+f"(c[2]), "+f"(c[3])
        : "r"(a[0]), "r"(a[1]), "r"(a[2]), "r"(a[3]), "r"(b0), "r"(b1));
}

__device__ __forceinline__ uint32_t packh2(float a, float b)
{
    __half2 p = __floats2half2_rn(a, b);
    return *reinterpret_cast<uint32_t*>(&p);
}

// ============================================================================
// fp16 tensor-core GEMM: BM=128, BN=64, BK=64 halves, 3-stage cp.async,
// 8 warps (4x2), warp tile 32x32, 72KB smem -> 3 CTAs/SM (24 warps/SM).
// ============================================================================
#define BM 128
#define BN 64
#define BK 64
#define STAGES 3
#define A_ST_BYTES (BM * 128)   // 16384
#define B_ST_BYTES (BN * 128)   // 8192
#define GEMM_SMEM (STAGES * (A_ST_BYTES + B_ST_BYTES))   // 73728

enum { EPI_NONE = 0, EPI_GELU = 1, EPI_RES = 2, EPI_RES_REMAP = 3 };

// tanh-form GELU using HW tanh.approx.f32
__device__ __forceinline__ float gelu_tanh(float x)
{
    float x3 = x * x * x;
    float u = 0.79788456080286536f * x + 0.03567740814255914f * x3;
    float t;
    asm("tanh.approx.f32 %0, %1;" : "=f"(t) : "f"(u));
    return 0.5f * x * (1.0f + t);
}

template <int EPI, bool OUT_HALF, int KC>
__global__ void __launch_bounds__(256, 3) gemm_fp16_kernel(
    const __half* __restrict__ A, const __half* __restrict__ Bw,
    const float* __restrict__ bias, const __half* __restrict__ res,
    void* __restrict__ CoutV, int N)
{
    extern __shared__ char smem[];
    const uint32_t sbase = smem_u32(smem);
    const uint32_t boff  = STAGES * A_ST_BYTES;

    const int tid  = threadIdx.x;
    const int warp = tid >> 5, lane = tid & 31;
    const int wm = warp >> 1, wn = warp & 1;   // 4x2: warp tile 32x32

    const size_t rowA = (size_t)blockIdx.y * BM;
    const size_t rowB = (size_t)blockIdx.x * BN;

    float acc[2][4][4];
    #pragma unroll
    for (int mt = 0; mt < 2; mt++)
        #pragma unroll
        for (int nt = 0; nt < 4; nt++)
            #pragma unroll
            for (int i = 0; i < 4; i++) acc[mt][nt][i] = 0.0f;

    constexpr int T = KC / BK;
    static_assert(T % STAGES == 0, "unroll-3 slot specialization needs T % 3 == 0");

    uint32_t swz[4];
    #pragma unroll
    for (int ks = 0; ks < 4; ks++)
        swz[ks] = (uint32_t)((((ks * 2 + (lane >> 4)) ^ (lane & 7)) << 4));
    const uint32_t rA0 = (uint32_t)((wm * 32 + (lane & 15)) * 128);
    const uint32_t rB0 = (uint32_t)((wn * 32 + (lane & 15)) * 128);

    // hoisted per-thread cp.async addressing
    const int r_c  = tid >> 3;          // A row for i=0 (step 32); B row = r_c&63? see below
    const int ci_c = tid & 7;
    const uint32_t sdstA = (uint32_t)(r_c * 128 + ((ci_c ^ (r_c & 7)) << 4));
    const __half* aSrc0 = A + (rowA + r_c) * KC + ci_c * 8;
    // B: 512 chunks (64 rows x 8): threads 0..511 -> row tid>>3 (0..63)... with
    // 256 threads, 2 iterations of 256: rows 0..31 (i=0), 32..63 (i=1).
    const int rb_c = tid >> 3;          // 0..31 for i=0
    const uint32_t sdstB = (uint32_t)(rb_c * 128 + ((ci_c ^ (rb_c & 7)) << 4));
    const __half* bSrc0 = Bw + (rowB + rb_c) * KC + ci_c * 8;

    auto loadStage = [&](int t, int slot) {
        const int k0 = t * BK;
        const uint32_t as = sbase + slot * A_ST_BYTES + sdstA;
        const uint32_t bs = sbase + boff + slot * B_ST_BYTES + sdstB;
        const __half* ap = aSrc0 + k0;
        const __half* bp = bSrc0 + k0;
        #pragma unroll
        for (int i = 0; i < 4; i++)
            cp16(as + i * (32 * 128), ap + (size_t)(32 * i) * KC);
        #pragma unroll
        for (int i = 0; i < 2; i++)
            cp16(bs + i * (32 * 128), bp + (size_t)(32 * i) * KC);
    };

    loadStage(0, 0); CP_COMMIT();
    loadStage(1, 1); CP_COMMIT();

    #pragma unroll 3
    for (int t = 0; t < T; t++) {
        const int slot = t % STAGES;
        CP_WAIT1();
        __syncthreads();
        if (t + 2 < T) loadStage(t + 2, (t + 2) % STAGES);
        CP_COMMIT();

        const uint32_t as = sbase + slot * A_ST_BYTES + rA0;
        const uint32_t bs = sbase + boff + slot * B_ST_BYTES + rB0;
        #pragma unroll
        for (int ks = 0; ks < 4; ks++) {
            const uint32_t sw = swz[ks];
            uint32_t af[2][4];
            #pragma unroll
            for (int mt = 0; mt < 2; mt++)
                ldsm_x4(af[mt], as + mt * 2048 + sw);
            uint32_t bf[2][4];
            #pragma unroll
            for (int np = 0; np < 2; np++)
                ldsm_x4(bf[np], bs + np * 2048 + sw);
            #pragma unroll
            for (int mt = 0; mt < 2; mt++)
                #pragma unroll
                for (int np = 0; np < 2; np++) {
                    mma_fp16(acc[mt][2*np  ], af[mt], bf[np][0], bf[np][2]);
                    mma_fp16(acc[mt][2*np+1], af[mt], bf[np][1], bf[np][3]);
                }
        }
    }

    // epilogue
    #pragma unroll
    for (int mt = 0; mt < 2; mt++) {
        #pragma unroll
        for (int rr = 0; rr < 2; rr++) {
            size_t gr = rowA + wm * 32 + mt * 16 + (lane >> 2) + rr * 8;
            size_t orow = gr;
            if (EPI == EPI_RES_REMAP) {
                int w = (int)(gr >> 7), n = (int)(gr & 127);
                orow = (size_t)(w >> 4) * 2048 + (n >> 4) * 256 + (w & 15) * 16 + (n & 15);
            }
            #pragma unroll
            for (int nt = 0; nt < 4; nt++) {
                int gc = blockIdx.x * BN + wn * 32 + nt * 8 + 2 * (lane & 3);
                float v0 = acc[mt][nt][rr * 2 + 0] + bias[gc];
                float v1 = acc[mt][nt][rr * 2 + 1] + bias[gc + 1];
                if (EPI == EPI_GELU) { v0 = gelu_tanh(v0); v1 = gelu_tanh(v1); }
                if (EPI == EPI_RES || EPI == EPI_RES_REMAP) {
                    __half2 rh = *(const __half2*)(res + gr * N + gc);
                    float2 rv = __half22float2(rh);
                    v0 += rv.x; v1 += rv.y;
                }
                if (OUT_HALF) {
                    __half2* op = (__half2*)((__half*)CoutV + orow * N + gc);
                    *op = __floats2half2_rn(v0, v1);
                } else {
                    float2* op = (float2*)((float*)CoutV + orow * N + gc);
                    *op = make_float2(v0, v1);
                }
            }
        }
    }
}

// ============================================================================
// Tensor-core windowed attention: block per (window, head), 4 warps.
// ============================================================================
#define AQ_OFF 0
#define AK_OFF 16384
#define AV_OFF 32768

__global__ void __launch_bounds__(128) attn_kernel(
    const float* __restrict__ qg, const __half* __restrict__ kv,
    const float* __restrict__ biasN, __half* __restrict__ ao)
{
    __shared__ __half smh[3 * NTOK * 64];
    const uint32_t sb = smem_u32(smh);

    const int w = blockIdx.x, h = blockIdx.y, n = threadIdx.x;
    const int warp = n >> 5, lane = n & 31;
    const int g = lane >> 2, tg = lane & 3;
    const int b = w >> 4;
    const float scale = 0.14433756729740643f;

    {
        const __half* krow = kv + ((size_t)w * NTOK + n) * KV_DIM + h * HEADD;
        const __half* vrow = krow + C_DIM;
        const uint32_t kdst = sb + AK_OFF + n * 128;
        const uint32_t vdst = sb + AV_OFF + n * 128;
        #pragma unroll
        for (int ci = 0; ci < 6; ci++) {
            int sg = (ci ^ (n & 7)) << 4;
            cp16(kdst + sg, krow + ci * 8);
            cp16(vdst + sg, vrow + ci * 8);
        }
        CP_COMMIT();

        const float* qrow = qg + (((size_t)b * NHEAD + h) * NTOK + n) * HEADD;
        char* smb = (char*)smh;
        #pragma unroll
        for (int ci = 0; ci < 6; ci++) {
            int sg = (ci ^ (n & 7)) << 4;
            float4 f0 = *(const float4*)(qrow + ci * 8);
            float4 f1 = *(const float4*)(qrow + ci * 8 + 4);
            __half2 q2[4];
            q2[0] = __floats2half2_rn(f0.x * scale, f0.y * scale);
            q2[1] = __floats2half2_rn(f0.z * scale, f0.w * scale);
            q2[2] = __floats2half2_rn(f1.x * scale, f1.y * scale);
            q2[3] = __floats2half2_rn(f1.z * scale, f1.w * scale);
            *(uint4*)(smb + AQ_OFF + n * 128 + sg) = *(uint4*)q2;
        }
        CP_WAIT0();
    }
    __syncthreads();

    const int r0 = warp * 32;

    uint32_t qa[2][3][4];
    #pragma unroll
    for (int mt = 0; mt < 2; mt++)
        #pragma unroll
        for (int ks = 0; ks < 3; ks++) {
            int r = r0 + mt * 16 + (lane & 15);
            int c = ks * 2 + (lane >> 4);
            ldsm_x4(qa[mt][ks], sb + AQ_OFF + r * 128 + ((c ^ (r & 7)) << 4));
        }

    #pragma unroll
    for (int mt = 0; mt < 2; mt++) {
        float sacc[16][4];
        #pragma unroll
        for (int nt = 0; nt < 16; nt++)
            #pragma unroll
            for (int i = 0; i < 4; i++) sacc[nt][i] = 0.0f;

        #pragma unroll
        for (int ks = 0; ks < 3; ks++) {
            #pragma unroll
            for (int ntp = 0; ntp < 8; ntp++) {
                uint32_t kb[4];
                int row = ntp * 16 + (lane & 7) + ((lane >> 4) << 3);
                int c = ks * 2 + ((lane >> 3) & 1);
                ldsm_x4(kb, sb + AK_OFF + row * 128 + ((c ^ (row & 7)) << 4));
                mma_fp16(sacc[2 * ntp    ], qa[mt][ks], kb[0], kb[1]);
                mma_fp16(sacc[2 * ntp + 1], qa[mt][ks], kb[2], kb[3]);
            }
        }

        int row0 = r0 + mt * 16 + g;
        const float* bp0 = biasN + ((size_t)h * NTOK + row0) * NTOK;
        const float* bp1 = bp0 + 8 * NTOK;
        float sum0 = 0.0f, sum1 = 0.0f;
        #pragma unroll
        for (int nt = 0; nt < 16; nt++) {
            int m0 = nt * 8 + tg * 2;
            float2 b0 = *(const float2*)(bp0 + m0);
            float2 b1 = *(const float2*)(bp1 + m0);
            float e0 = __expf(sacc[nt][0] + b0.x - 4.0f);
            float e1 = __expf(sacc[nt][1] + b0.y - 4.0f);
            float e2 = __expf(sacc[nt][2] + b1.x - 4.0f);
            float e3 = __expf(sacc[nt][3] + b1.y - 4.0f);
            sacc[nt][0] = e0; sacc[nt][1] = e1;
            sacc[nt][2] = e2; sacc[nt][3] = e3;
            sum0 += e0 + e1; sum1 += e2 + e3;
        }
        sum0 += __shfl_xor_sync(0xffffffffu, sum0, 1);
        sum0 += __shfl_xor_sync(0xffffffffu, sum0, 2);
        sum1 += __shfl_xor_sync(0xffffffffu, sum1, 1);
        sum1 += __shfl_xor_sync(0xffffffffu, sum1, 2);
        float inv0 = 1.0f / sum0, inv1 = 1.0f / sum1;

        float oacc[6][4];
        #pragma unroll
        for (int nt = 0; nt < 6; nt++)
            #pragma unroll
            for (int i = 0; i < 4; i++) oacc[nt][i] = 0.0f;

        #pragma unroll
        for (int ks2 = 0; ks2 < 8; ks2++) {
            uint32_t pa[4];
            pa[0] = packh2(sacc[2 * ks2    ][0], sacc[2 * ks2    ][1]);
            pa[1] = packh2(sacc[2 * ks2    ][2], sacc[2 * ks2    ][3]);
            pa[2] = packh2(sacc[2 * ks2 + 1][0], sacc[2 * ks2 + 1][1]);
            pa[3] = packh2(sacc[2 * ks2 + 1][2], sacc[2 * ks2 + 1][3]);
            #pragma unroll
            for (int np = 0; np < 3; np++) {
                uint32_t vb[4];
                int row = ks2 * 16 + (lane & 7) + (((lane >> 3) & 1) << 3);
                int c = np * 2 + (lane >> 4);
                ldsm_x4_t(vb, sb + AV_OFF + row * 128 + ((c ^ (row & 7)) << 4));
                mma_fp16(oacc[2 * np    ], pa, vb[0], vb[1]);
                mma_fp16(oacc[2 * np + 1], pa, vb[2], vb[3]);
            }
        }

        __half* aobase = ao + (size_t)w * NTOK * C_DIM + h * HEADD;
        #pragma unroll
        for (int nt = 0; nt < 6; nt++) {
            int col = nt * 8 + tg * 2;
            *(__half2*)(aobase + (size_t)row0 * C_DIM + col) =
                __floats2half2_rn(oacc[nt][0] * inv0, oacc[nt][1] * inv0);
            *(__half2*)(aobase + (size_t)(row0 + 8) * C_DIM + col) =
                __floats2half2_rn(oacc[nt][2] * inv1, oacc[nt][3] * inv1);
        }
    }
}

// ----------------------------------------------------------------------------
extern "C" void kernel_launch(void* const* d_in, const int* in_sizes, int n_in,
                              void* d_out, int out_size)
{
    const float* x    = (const float*)d_in[0];
    const float* qg   = (const float*)d_in[1];
    const float* n1g  = (const float*)d_in[2];
    const float* n1b  = (const float*)d_in[3];
    const float* qkvw = (const float*)d_in[4];
    const float* qkvb = (const float*)d_in[5];
    const float* rpb  = (const float*)d_in[6];
    const float* pw   = (const float*)d_in[7];
    const float* pb   = (const float*)d_in[8];
    const float* n2g  = (const float*)d_in[9];
    const float* n2b  = (const float*)d_in[10];
    const float* f1w  = (const float*)d_in[11];
    const float* f1b  = (const float*)d_in[12];
    const float* f2w  = (const float*)d_in[13];
    const float* f2b  = (const float*)d_in[14];
    float* out = (float*)d_out;

    __half *xln16, *kv16, *ao16, *xa16, *ln216, *hmid16, *qkvw16, *pw16, *f1w16, *f2w16;
    float *biasN;
    cudaGetSymbolAddress((void**)&xln16,  g_xln16);
    cudaGetSymbolAddress((void**)&kv16,   g_kv16);
    cudaGetSymbolAddress((void**)&ao16,   g_ao16);
    cudaGetSymbolAddress((void**)&xa16,   g_xa16);
    cudaGetSymbolAddress((void**)&ln216,  g_ln216);
    cudaGetSymbolAddress((void**)&hmid16, g_hmid16);
    cudaGetSymbolAddress((void**)&qkvw16, g_qkvw16);
    cudaGetSymbolAddress((void**)&pw16,   g_pw16);
    cudaGetSymbolAddress((void**)&f1w16,  g_f1w16);
    cudaGetSymbolAddress((void**)&f2w16,  g_f2w16);
    cudaGetSymbolAddress((void**)&biasN,  g_biasN);

    cudaFuncSetAttribute((const void*)gemm_fp16_kernel<EPI_NONE, true, C_DIM>,
                         cudaFuncAttributeMaxDynamicSharedMemorySize, GEMM_SMEM);
    cudaFuncSetAttribute((const void*)gemm_fp16_kernel<EPI_RES, true, C_DIM>,
                         cudaFuncAttributeMaxDynamicSharedMemorySize, GEMM_SMEM);
    cudaFuncSetAttribute((const void*)gemm_fp16_kernel<EPI_GELU, true, C_DIM>,
                         cudaFuncAttributeMaxDynamicSharedMemorySize, GEMM_SMEM);
    cudaFuncSetAttribute((const void*)gemm_fp16_kernel<EPI_RES_REMAP, false, HID_DIM>,
                         cudaFuncAttributeMaxDynamicSharedMemorySize, GEMM_SMEM);

    // 1) merged preamble: LN1+window-partition | bias table | weight converts
    preamble_kernel<<<PRE_GRID, 256>>>(x, n1g, n1b, xln16, rpb, biasN,
                                       qkvw, qkvw16, pw, pw16,
                                       f1w, f1w16, f2w, f2w16);

    // 2) KV projection -> fp16
    gemm_fp16_kernel<EPI_NONE, true, C_DIM>
        <<<dim3(KV_DIM / BN, M_ROWS / BM), 256, GEMM_SMEM>>>(
        xln16, qkvw16, qkvb, nullptr, kv16, KV_DIM);

    // 3) windowed attention (tensor cores) -> fp16
    attn_kernel<<<dim3(NWIN, NHEAD), 128>>>(qg, kv16, biasN, ao16);

    // 4) proj + residual(xln16) -> xa16 (fp16)
    gemm_fp16_kernel<EPI_RES, true, C_DIM>
        <<<dim3(C_DIM / BN, M_ROWS / BM), 256, GEMM_SMEM>>>(
        ao16, pw16, pb, xln16, xa16, C_DIM);

    // 5) LN2 (fp16 in/out, vectorized)
    ln2_kernel<<<M_ROWS, 128>>>(xa16, n2g, n2b, ln216);

    // 6) fc1 + GELU(tanh HW) -> fp16
    gemm_fp16_kernel<EPI_GELU, true, C_DIM>
        <<<dim3(HID_DIM / BN, M_ROWS / BM), 256, GEMM_SMEM>>>(
        ln216, f1w16, f1b, nullptr, hmid16, HID_DIM);

    // 7) fc2 + residual(xa16) + window reverse -> out fp32
    gemm_fp16_kernel<EPI_RES_REMAP, false, HID_DIM>
        <<<dim3(C_DIM / BN, M_ROWS / BM), 256, GEMM_SMEM>>>(
        hmid16, f2w16, f2b, xa16, out, C_DIM);
}

// round 17
// speedup vs baseline: 1.0629x; 1.0629x over previous
#include <cuda_runtime.h>
#include <cuda_fp16.h>
#include <cstdint>
#include <math.h>

// ----------------------------------------------------------------------------
// GCViT block, shapes fixed: B=32, H=8, W=256, C=768, NH=16, HD=48
// windows: wh=8, ww=16 -> N=128 tokens/window, Bw=512, M = 65536 rows
// ----------------------------------------------------------------------------

#define M_ROWS   65536
#define C_DIM    768
#define KV_DIM   1536
#define HID_DIM  3072
#define NHEAD    16
#define HEADD    48
#define NTOK     128
#define NWIN     512

// fp16 activations / weights
__device__ __half g_xln16 [ (size_t)M_ROWS * C_DIM  ];
__device__ __half g_kv16  [ (size_t)M_ROWS * KV_DIM ];
__device__ __half g_ao16  [ (size_t)M_ROWS * C_DIM  ];
__device__ __half g_xa16  [ (size_t)M_ROWS * C_DIM  ];
__device__ __half g_ln216 [ (size_t)M_ROWS * C_DIM  ];
__device__ __half g_hmid16[ (size_t)M_ROWS * HID_DIM];
__device__ __half g_qkvw16[ (size_t)KV_DIM * C_DIM  ];
__device__ __half g_pw16  [ (size_t)C_DIM * C_DIM   ];
__device__ __half g_f1w16 [ (size_t)HID_DIM * C_DIM ];
__device__ __half g_f2w16 [ (size_t)C_DIM * HID_DIM ];
// fp32
__device__ float g_biasN[ NHEAD * NTOK * NTOK ];   // [h][n][m]

// convert sizes (all divisible by 4)
#define CONV_N0 (KV_DIM * C_DIM)
#define CONV_N1 (C_DIM * C_DIM)
#define CONV_N2 (HID_DIM * C_DIM)
#define CONV_N3 (C_DIM * HID_DIM)
#define CONV_TOT4 ((CONV_N0 + CONV_N1 + CONV_N2 + CONV_N3) / 4)
#define CONV_BLOCKS ((CONV_TOT4 + 255) / 256)
#define PRE_GRID (M_ROWS + 128 + CONV_BLOCKS)

// ============================================================================
// merged preamble: LN1+window-partition | bias table | weight converts (x4)
// ============================================================================
__device__ __forceinline__ void conv4(const float* __restrict__ s,
                                      __half* __restrict__ d, int e)
{
    float4 v = *(const float4*)(s + e);
    __half2 h0 = __floats2half2_rn(v.x, v.y);
    __half2 h1 = __floats2half2_rn(v.z, v.w);
    uint2 pk = make_uint2(*(uint32_t*)&h0, *(uint32_t*)&h1);
    *(uint2*)(d + e) = pk;
}

__global__ void preamble_kernel(
    const float* __restrict__ x, const float* __restrict__ g,
    const float* __restrict__ bta, __half* __restrict__ xln16,
    const float* __restrict__ rpb, float* __restrict__ biasN,
    const float* __restrict__ qkvw, __half* __restrict__ qkvw16,
    const float* __restrict__ pw,   __half* __restrict__ pw16,
    const float* __restrict__ f1w,  __half* __restrict__ f1w16,
    const float* __restrict__ f2w,  __half* __restrict__ f2w16)
{
    const int blk = blockIdx.x;
    const int t = threadIdx.x;

    if (blk < M_ROWS) {
        __shared__ float s1[8], s2[8];
        const float* xr = x + (long)blk * C_DIM;
        float v0 = xr[t], v1 = xr[t + 256], v2 = xr[t + 512];
        float a = v0 + v1 + v2;
        float bsq = v0*v0 + v1*v1 + v2*v2;
        #pragma unroll
        for (int o = 16; o > 0; o >>= 1) {
            a   += __shfl_xor_sync(0xffffffffu, a, o);
            bsq += __shfl_xor_sync(0xffffffffu, bsq, o);
        }
        if ((t & 31) == 0) { s1[t >> 5] = a; s2[t >> 5] = bsq; }
        __syncthreads();
        float suma = 0.0f, sumb = 0.0f;
        #pragma unroll
        for (int i = 0; i < 8; i++) { suma += s1[i]; sumb += s2[i]; }
        float mean = suma * (1.0f / 768.0f);
        float var  = sumb * (1.0f / 768.0f) - mean * mean;
        float rstd = rsqrtf(var + 1e-5f);
        int bb = blk >> 11, l = blk & 2047;
        int rh = l >> 8, col = l & 255, wc = col >> 4, rw = col & 15;
        long orow = (long)(bb * 16 + wc) * NTOK + rh * 16 + rw;
        __half* o16 = xln16 + orow * C_DIM;
        o16[t]       = __float2half_rn((v0 - mean) * rstd * g[t]       + bta[t]);
        o16[t + 256] = __float2half_rn((v1 - mean) * rstd * g[t + 256] + bta[t + 256]);
        o16[t + 512] = __float2half_rn((v2 - mean) * rstd * g[t + 512] + bta[t + 512]);
        return;
    }
    if (blk < M_ROWS + 128) {
        if (t < 128) {
            int n = blk - M_ROWS, m = t;
            int drh = (n >> 4) - (m >> 4);
            int drw = (n & 15) - (m & 15);
            int idx = (drh + 7) * 63 + (drw + 31);
            #pragma unroll
            for (int h = 0; h < NHEAD; h++)
                biasN[h * (NTOK*NTOK) + n * NTOK + m] = rpb[idx * NHEAD + h];
        }
        return;
    }
    int i4 = (blk - M_ROWS - 128) * 256 + t;
    int e = i4 * 4;
    if (e < CONV_N0) { conv4(qkvw, qkvw16, e); return; }
    e -= CONV_N0;
    if (e < CONV_N1) { conv4(pw, pw16, e); return; }
    e -= CONV_N1;
    if (e < CONV_N2) { conv4(f1w, f1w16, e); return; }
    e -= CONV_N2;
    if (e < CONV_N3) { conv4(f2w, f2w16, e); }
}

// LayerNorm (LN2): fp16 in/out, 128 threads/row, __half2 vectorized accesses.
__global__ void __launch_bounds__(128) ln2_kernel(
    const __half* __restrict__ x, const float* __restrict__ g,
    const float* __restrict__ bta, __half* __restrict__ out16)
{
    __shared__ float s1[4], s2[4];
    int r = blockIdx.x, t = threadIdx.x;
    const __half2* xr = (const __half2*)(x + (long)r * C_DIM);
    __half2 h0 = xr[t], h1 = xr[t + 128], h2 = xr[t + 256];
    float2 f0 = __half22float2(h0);
    float2 f1 = __half22float2(h1);
    float2 f2 = __half22float2(h2);
    float a = f0.x + f0.y + f1.x + f1.y + f2.x + f2.y;
    float bsq = f0.x*f0.x + f0.y*f0.y + f1.x*f1.x + f1.y*f1.y + f2.x*f2.x + f2.y*f2.y;
    #pragma unroll
    for (int o = 16; o > 0; o >>= 1) {
        a   += __shfl_xor_sync(0xffffffffu, a, o);
        bsq += __shfl_xor_sync(0xffffffffu, bsq, o);
    }
    if ((t & 31) == 0) { s1[t >> 5] = a; s2[t >> 5] = bsq; }
    __syncthreads();
    float suma = s1[0] + s1[1] + s1[2] + s1[3];
    float sumb = s2[0] + s2[1] + s2[2] + s2[3];
    float mean = suma * (1.0f / 768.0f);
    float var  = sumb * (1.0f / 768.0f) - mean * mean;
    float rstd = rsqrtf(var + 1e-5f);

    const float2* gp = (const float2*)g;
    const float2* bp = (const float2*)bta;
    __half2* o16 = (__half2*)(out16 + (long)r * C_DIM);
    float2 g0 = gp[t], g1 = gp[t + 128], g2 = gp[t + 256];
    float2 b0 = bp[t], b1 = bp[t + 128], b2 = bp[t + 256];
    o16[t] = __floats2half2_rn((f0.x - mean) * rstd * g0.x + b0.x,
                               (f0.y - mean) * rstd * g0.y + b0.y);
    o16[t + 128] = __floats2half2_rn((f1.x - mean) * rstd * g1.x + b1.x,
                                     (f1.y - mean) * rstd * g1.y + b1.y);
    o16[t + 256] = __floats2half2_rn((f2.x - mean) * rstd * g2.x + b2.x,
                                     (f2.y - mean) * rstd * g2.y + b2.y);
}

// ============================================================================
// shared PTX helpers
// ============================================================================
__device__ __forceinline__ uint32_t smem_u32(const void* p)
{
    uint32_t a;
    asm("{ .reg .u64 t; cvta.to.shared.u64 t, %1; cvt.u32.u64 %0, t; }"
        : "=r"(a) : "l"(p));
    return a;
}

__device__ __forceinline__ void cp16(uint32_t smem, const void* gmem)
{
    asm volatile("cp.async.cg.shared.global.L2::256B [%0], [%1], 16;"
                 :: "r"(smem), "l"(gmem));
}
#define CP_COMMIT() asm volatile("cp.async.commit_group;")
#define CP_WAIT1()  asm volatile("cp.async.wait_group 1;")
#define CP_WAIT0()  asm volatile("cp.async.wait_group 0;")

__device__ __forceinline__ void ldsm_x4(uint32_t r[4], uint32_t addr)
{
    asm volatile("ldmatrix.sync.aligned.m8n8.x4.shared.b16 {%0,%1,%2,%3}, [%4];"
                 : "=r"(r[0]), "=r"(r[1]), "=r"(r[2]), "=r"(r[3]) : "r"(addr));
}

__device__ __forceinline__ void ldsm_x4_t(uint32_t r[4], uint32_t addr)
{
    asm volatile("ldmatrix.sync.aligned.m8n8.x4.trans.shared.b16 {%0,%1,%2,%3}, [%4];"
                 : "=r"(r[0]), "=r"(r[1]), "=r"(r[2]), "=r"(r[3]) : "r"(addr));
}

__device__ __forceinline__ void mma_fp16(float c[4], const uint32_t a[4],
                                         uint32_t b0, uint32_t b1)
{
    asm volatile(
        "mma.sync.aligned.m16n8k16.row.col.f32.f16.f16.f32 "
        "{%0,%1,%2,%3},{%4,%5,%6,%7},{%8,%9},{%0,%1,%2,%3};"
        : "+f"(c[0]), "+f"(c[1]), "+f"(c[2]), "+f"(c[3])
        : "r"(a[0]), "r"(a[1]), "r"(a[2]), "r"(a[3]), "r"(b0), "r"(b1));
}

__device__ __forceinline__ uint32_t packh2(float a, float b)
{
    __half2 p = __floats2half2_rn(a, b);
    return *reinterpret_cast<uint32_t*>(&p);
}

// ============================================================================
// fp16 tensor-core GEMM (R15 config): BM=128, BN=128, BK=64 halves, 3-stage
// cp.async, 8 warps (4x2), warp tile 32x64, 2 CTAs/SM, unroll-3 slots,
// hoisted cp.async addressing; float2 bias loads in epilogue.
// ============================================================================
#define BM 128
#define BN 128
#define BK 64
#define STAGES 3
#define A_ST_BYTES (BM * 128)
#define B_ST_BYTES (BN * 128)
#define GEMM_SMEM (STAGES * (A_ST_BYTES + B_ST_BYTES))   // 98304

enum { EPI_NONE = 0, EPI_GELU = 1, EPI_RES = 2, EPI_RES_REMAP = 3 };

// tanh-form GELU using HW tanh.approx.f32
__device__ __forceinline__ float gelu_tanh(float x)
{
    float x3 = x * x * x;
    float u = 0.79788456080286536f * x + 0.03567740814255914f * x3;
    float t;
    asm("tanh.approx.f32 %0, %1;" : "=f"(t) : "f"(u));
    return 0.5f * x * (1.0f + t);
}

template <int EPI, bool OUT_HALF, int KC>
__global__ void __launch_bounds__(256, 2) gemm_fp16_kernel(
    const __half* __restrict__ A, const __half* __restrict__ Bw,
    const float* __restrict__ bias, const __half* __restrict__ res,
    void* __restrict__ CoutV, int N)
{
    extern __shared__ char smem[];
    const uint32_t sbase = smem_u32(smem);
    const uint32_t boff  = STAGES * A_ST_BYTES;

    const int tid  = threadIdx.x;
    const int warp = tid >> 5, lane = tid & 31;
    const int wm = warp >> 1, wn = warp & 1;

    const size_t rowA = (size_t)blockIdx.y * BM;
    const size_t rowB = (size_t)blockIdx.x * BN;

    float acc[2][8][4];
    #pragma unroll
    for (int mt = 0; mt < 2; mt++)
        #pragma unroll
        for (int nt = 0; nt < 8; nt++)
            #pragma unroll
            for (int i = 0; i < 4; i++) acc[mt][nt][i] = 0.0f;

    constexpr int T = KC / BK;
    static_assert(T % STAGES == 0, "unroll-3 slot specialization needs T % 3 == 0");

    uint32_t swz[4];
    #pragma unroll
    for (int ks = 0; ks < 4; ks++)
        swz[ks] = (uint32_t)((((ks * 2 + (lane >> 4)) ^ (lane & 7)) << 4));
    const uint32_t rA0 = (uint32_t)((wm * 32 + (lane & 15)) * 128);
    const uint32_t rB0 = (uint32_t)((wn * 64 + (lane & 15)) * 128);

    // hoisted per-thread cp.async addressing
    const int r_c  = tid >> 3;
    const int ci_c = tid & 7;
    const uint32_t sdst0 = (uint32_t)(r_c * 128 + ((ci_c ^ (r_c & 7)) << 4));
    const __half* aSrc0 = A  + (rowA + r_c) * KC + ci_c * 8;
    const __half* bSrc0 = Bw + (rowB + r_c) * KC + ci_c * 8;

    auto loadStage = [&](int t, int slot) {
        const int k0 = t * BK;
        const uint32_t as = sbase + slot * A_ST_BYTES + sdst0;
        const uint32_t bs = sbase + boff + slot * B_ST_BYTES + sdst0;
        const __half* ap = aSrc0 + k0;
        const __half* bp = bSrc0 + k0;
        #pragma unroll
        for (int i = 0; i < 4; i++)
            cp16(as + i * (32 * 128), ap + (size_t)(32 * i) * KC);
        #pragma unroll
        for (int i = 0; i < 4; i++)
            cp16(bs + i * (32 * 128), bp + (size_t)(32 * i) * KC);
    };

    loadStage(0, 0); CP_COMMIT();
    loadStage(1, 1); CP_COMMIT();

    #pragma unroll 3
    for (int t = 0; t < T; t++) {
        const int slot = t % STAGES;
        CP_WAIT1();
        __syncthreads();
        if (t + 2 < T) loadStage(t + 2, (t + 2) % STAGES);
        CP_COMMIT();

        const uint32_t as = sbase + slot * A_ST_BYTES + rA0;
        const uint32_t bs = sbase + boff + slot * B_ST_BYTES + rB0;
        #pragma unroll
        for (int ks = 0; ks < 4; ks++) {
            const uint32_t sw = swz[ks];
            uint32_t af[2][4];
            #pragma unroll
            for (int mt = 0; mt < 2; mt++)
                ldsm_x4(af[mt], as + mt * 2048 + sw);
            uint32_t bf[4][4];
            #pragma unroll
            for (int np = 0; np < 4; np++)
                ldsm_x4(bf[np], bs + np * 2048 + sw);
            #pragma unroll
            for (int mt = 0; mt < 2; mt++)
                #pragma unroll
                for (int np = 0; np < 4; np++) {
                    mma_fp16(acc[mt][2*np  ], af[mt], bf[np][0], bf[np][2]);
                    mma_fp16(acc[mt][2*np+1], af[mt], bf[np][1], bf[np][3]);
                }
        }
    }

    // epilogue (float2 bias loads; gc is 8B-aligned)
    #pragma unroll
    for (int mt = 0; mt < 2; mt++) {
        #pragma unroll
        for (int rr = 0; rr < 2; rr++) {
            size_t gr = rowA + wm * 32 + mt * 16 + (lane >> 2) + rr * 8;
            size_t orow = gr;
            if (EPI == EPI_RES_REMAP) {
                int w = (int)(gr >> 7), n = (int)(gr & 127);
                orow = (size_t)(w >> 4) * 2048 + (n >> 4) * 256 + (w & 15) * 16 + (n & 15);
            }
            #pragma unroll
            for (int nt = 0; nt < 8; nt++) {
                int gc = blockIdx.x * BN + wn * 64 + nt * 8 + 2 * (lane & 3);
                float2 bi = *(const float2*)(bias + gc);
                float v0 = acc[mt][nt][rr * 2 + 0] + bi.x;
                float v1 = acc[mt][nt][rr * 2 + 1] + bi.y;
                if (EPI == EPI_GELU) { v0 = gelu_tanh(v0); v1 = gelu_tanh(v1); }
                if (EPI == EPI_RES || EPI == EPI_RES_REMAP) {
                    __half2 rh = *(const __half2*)(res + gr * N + gc);
                    float2 rv = __half22float2(rh);
                    v0 += rv.x; v1 += rv.y;
                }
                if (OUT_HALF) {
                    __half2* op = (__half2*)((__half*)CoutV + orow * N + gc);
                    *op = __floats2half2_rn(v0, v1);
                } else {
                    float2* op = (float2*)((float*)CoutV + orow * N + gc);
                    *op = make_float2(v0, v1);
                }
            }
        }
    }
}

// ============================================================================
// Tensor-core windowed attention: block per (window, head), 4 warps.
// ============================================================================
#define AQ_OFF 0
#define AK_OFF 16384
#define AV_OFF 32768

__global__ void __launch_bounds__(128) attn_kernel(
    const float* __restrict__ qg, const __half* __restrict__ kv,
    const float* __restrict__ biasN, __half* __restrict__ ao)
{
    __shared__ __half smh[3 * NTOK * 64];
    const uint32_t sb = smem_u32(smh);

    const int w = blockIdx.x, h = blockIdx.y, n = threadIdx.x;
    const int warp = n >> 5, lane = n & 31;
    const int g = lane >> 2, tg = lane & 3;
    const int b = w >> 4;
    const float scale = 0.14433756729740643f;

    {
        const __half* krow = kv + ((size_t)w * NTOK + n) * KV_DIM + h * HEADD;
        const __half* vrow = krow + C_DIM;
        const uint32_t kdst = sb + AK_OFF + n * 128;
        const uint32_t vdst = sb + AV_OFF + n * 128;
        #pragma unroll
        for (int ci = 0; ci < 6; ci++) {
            int sg = (ci ^ (n & 7)) << 4;
            cp16(kdst + sg, krow + ci * 8);
            cp16(vdst + sg, vrow + ci * 8);
        }
        CP_COMMIT();

        const float* qrow = qg + (((size_t)b * NHEAD + h) * NTOK + n) * HEADD;
        char* smb = (char*)smh;
        #pragma unroll
        for (int ci = 0; ci < 6; ci++) {
            int sg = (ci ^ (n & 7)) << 4;
            float4 f0 = *(const float4*)(qrow + ci * 8);
            float4 f1 = *(const float4*)(qrow + ci * 8 + 4);
            __half2 q2[4];
            q2[0] = __floats2half2_rn(f0.x * scale, f0.y * scale);
            q2[1] = __floats2half2_rn(f0.z * scale, f0.w * scale);
            q2[2] = __floats2half2_rn(f1.x * scale, f1.y * scale);
            q2[3] = __floats2half2_rn(f1.z * scale, f1.w * scale);
            *(uint4*)(smb + AQ_OFF + n * 128 + sg) = *(uint4*)q2;
        }
        CP_WAIT0();
    }
    __syncthreads();

    const int r0 = warp * 32;

    uint32_t qa[2][3][4];
    #pragma unroll
    for (int mt = 0; mt < 2; mt++)
        #pragma unroll
        for (int ks = 0; ks < 3; ks++) {
            int r = r0 + mt * 16 + (lane & 15);
            int c = ks * 2 + (lane >> 4);
            ldsm_x4(qa[mt][ks], sb + AQ_OFF + r * 128 + ((c ^ (r & 7)) << 4));
        }

    #pragma unroll
    for (int mt = 0; mt < 2; mt++) {
        float sacc[16][4];
        #pragma unroll
        for (int nt = 0; nt < 16; nt++)
            #pragma unroll
            for (int i = 0; i < 4; i++) sacc[nt][i] = 0.0f;

        #pragma unroll
        for (int ks = 0; ks < 3; ks++) {
            #pragma unroll
            for (int ntp = 0; ntp < 8; ntp++) {
                uint32_t kb[4];
                int row = ntp * 16 + (lane & 7) + ((lane >> 4) << 3);
                int c = ks * 2 + ((lane >> 3) & 1);
                ldsm_x4(kb, sb + AK_OFF + row * 128 + ((c ^ (row & 7)) << 4));
                mma_fp16(sacc[2 * ntp    ], qa[mt][ks], kb[0], kb[1]);
                mma_fp16(sacc[2 * ntp + 1], qa[mt][ks], kb[2], kb[3]);
            }
        }

        int row0 = r0 + mt * 16 + g;
        const float* bp0 = biasN + ((size_t)h * NTOK + row0) * NTOK;
        const float* bp1 = bp0 + 8 * NTOK;
        float sum0 = 0.0f, sum1 = 0.0f;
        #pragma unroll
        for (int nt = 0; nt < 16; nt++) {
            int m0 = nt * 8 + tg * 2;
            float2 b0 = *(const float2*)(bp0 + m0);
            float2 b1 = *(const float2*)(bp1 + m0);
            float e0 = __expf(sacc[nt][0] + b0.x - 4.0f);
            float e1 = __expf(sacc[nt][1] + b0.y - 4.0f);
            float e2 = __expf(sacc[nt][2] + b1.x - 4.0f);
            float e3 = __expf(sacc[nt][3] + b1.y - 4.0f);
            sacc[nt][0] = e0; sacc[nt][1] = e1;
            sacc[nt][2] = e2; sacc[nt][3] = e3;
            sum0 += e0 + e1; sum1 += e2 + e3;
        }
        sum0 += __shfl_xor_sync(0xffffffffu, sum0, 1);
        sum0 += __shfl_xor_sync(0xffffffffu, sum0, 2);
        sum1 += __shfl_xor_sync(0xffffffffu, sum1, 1);
        sum1 += __shfl_xor_sync(0xffffffffu, sum1, 2);
        float inv0 = 1.0f / sum0, inv1 = 1.0f / sum1;

        float oacc[6][4];
        #pragma unroll
        for (int nt = 0; nt < 6; nt++)
            #pragma unroll
            for (int i = 0; i < 4; i++) oacc[nt][i] = 0.0f;

        #pragma unroll
        for (int ks2 = 0; ks2 < 8; ks2++) {
            uint32_t pa[4];
            pa[0] = packh2(sacc[2 * ks2    ][0], sacc[2 * ks2    ][1]);
            pa[1] = packh2(sacc[2 * ks2    ][2], sacc[2 * ks2    ][3]);
            pa[2] = packh2(sacc[2 * ks2 + 1][0], sacc[2 * ks2 + 1][1]);
            pa[3] = packh2(sacc[2 * ks2 + 1][2], sacc[2 * ks2 + 1][3]);
            #pragma unroll
            for (int np = 0; np < 3; np++) {
                uint32_t vb[4];
                int row = ks2 * 16 + (lane & 7) + (((lane >> 3) & 1) << 3);
                int c = np * 2 + (lane >> 4);
                ldsm_x4_t(vb, sb + AV_OFF + row * 128 + ((c ^ (row & 7)) << 4));
                mma_fp16(oacc[2 * np    ], pa, vb[0], vb[1]);
                mma_fp16(oacc[2 * np + 1], pa, vb[2], vb[3]);
            }
        }

        __half* aobase = ao + (size_t)w * NTOK * C_DIM + h * HEADD;
        #pragma unroll
        for (int nt = 0; nt < 6; nt++) {
            int col = nt * 8 + tg * 2;
            *(__half2*)(aobase + (size_t)row0 * C_DIM + col) =
                __floats2half2_rn(oacc[nt][0] * inv0, oacc[nt][1] * inv0);
            *(__half2*)(aobase + (size_t)(row0 + 8) * C_DIM + col) =
                __floats2half2_rn(oacc[nt][2] * inv1, oacc[nt][3] * inv1);
        }
    }
}

// ----------------------------------------------------------------------------
extern "C" void kernel_launch(void* const* d_in, const int* in_sizes, int n_in,
                              void* d_out, int out_size)
{
    const float* x    = (const float*)d_in[0];
    const float* qg   = (const float*)d_in[1];
    const float* n1g  = (const float*)d_in[2];
    const float* n1b  = (const float*)d_in[3];
    const float* qkvw = (const float*)d_in[4];
    const float* qkvb = (const float*)d_in[5];
    const float* rpb  = (const float*)d_in[6];
    const float* pw   = (const float*)d_in[7];
    const float* pb   = (const float*)d_in[8];
    const float* n2g  = (const float*)d_in[9];
    const float* n2b  = (const float*)d_in[10];
    const float* f1w  = (const float*)d_in[11];
    const float* f1b  = (const float*)d_in[12];
    const float* f2w  = (const float*)d_in[13];
    const float* f2b  = (const float*)d_in[14];
    float* out = (float*)d_out;

    __half *xln16, *kv16, *ao16, *xa16, *ln216, *hmid16, *qkvw16, *pw16, *f1w16, *f2w16;
    float *biasN;
    cudaGetSymbolAddress((void**)&xln16,  g_xln16);
    cudaGetSymbolAddress((void**)&kv16,   g_kv16);
    cudaGetSymbolAddress((void**)&ao16,   g_ao16);
    cudaGetSymbolAddress((void**)&xa16,   g_xa16);
    cudaGetSymbolAddress((void**)&ln216,  g_ln216);
    cudaGetSymbolAddress((void**)&hmid16, g_hmid16);
    cudaGetSymbolAddress((void**)&qkvw16, g_qkvw16);
    cudaGetSymbolAddress((void**)&pw16,   g_pw16);
    cudaGetSymbolAddress((void**)&f1w16,  g_f1w16);
    cudaGetSymbolAddress((void**)&f2w16,  g_f2w16);
    cudaGetSymbolAddress((void**)&biasN,  g_biasN);

    cudaFuncSetAttribute((const void*)gemm_fp16_kernel<EPI_NONE, true, C_DIM>,
                         cudaFuncAttributeMaxDynamicSharedMemorySize, GEMM_SMEM);
    cudaFuncSetAttribute((const void*)gemm_fp16_kernel<EPI_RES, true, C_DIM>,
                         cudaFuncAttributeMaxDynamicSharedMemorySize, GEMM_SMEM);
    cudaFuncSetAttribute((const void*)gemm_fp16_kernel<EPI_GELU, true, C_DIM>,
                         cudaFuncAttributeMaxDynamicSharedMemorySize, GEMM_SMEM);
    cudaFuncSetAttribute((const void*)gemm_fp16_kernel<EPI_RES_REMAP, false, HID_DIM>,
                         cudaFuncAttributeMaxDynamicSharedMemorySize, GEMM_SMEM);

    // 1) merged preamble: LN1+window-partition | bias table | weight converts
    preamble_kernel<<<PRE_GRID, 256>>>(x, n1g, n1b, xln16, rpb, biasN,
                                       qkvw, qkvw16, pw, pw16,
                                       f1w, f1w16, f2w, f2w16);

    // 2) KV projection -> fp16
    gemm_fp16_kernel<EPI_NONE, true, C_DIM>
        <<<dim3(KV_DIM / BN, M_ROWS / BM), 256, GEMM_SMEM>>>(
        xln16, qkvw16, qkvb, nullptr, kv16, KV_DIM);

    // 3) windowed attention (tensor cores) -> fp16
    attn_kernel<<<dim3(NWIN, NHEAD), 128>>>(qg, kv16, biasN, ao16);

    // 4) proj + residual(xln16) -> xa16 (fp16)
    gemm_fp16_kernel<EPI_RES, true, C_DIM>
        <<<dim3(C_DIM / BN, M_ROWS / BM), 256, GEMM_SMEM>>>(
        ao16, pw16, pb, xln16, xa16, C_DIM);

    // 5) LN2 (fp16 in/out, vectorized)
    ln2_kernel<<<M_ROWS, 128>>>(xa16, n2g, n2b, ln216);

    // 6) fc1 + GELU(tanh HW) -> fp16
    gemm_fp16_kernel<EPI_GELU, true, C_DIM>
        <<<dim3(HID_DIM / BN, M_ROWS / BM), 256, GEMM_SMEM>>>(
        ln216, f1w16, f1b, nullptr, hmid16, HID_DIM);

    // 7) fc2 + residual(xa16) + window reverse -> out fp32
    gemm_fp16_kernel<EPI_RES_REMAP, false, HID_DIM>
        <<<dim3(C_DIM / BN, M_ROWS / BM), 256, GEMM_SMEM>>>(
        hmid16, f2w16, f2b, xa16, out, C_DIM);
}